// round 16
// baseline (speedup 1.0000x reference)
#include <cuda_runtime.h>
#include <stdint.h>
#include <math.h>

#define NB 4096
#define NS 64
#define NY 256
#define NH 128
#define NE 32
#define NKG 8
#define NKA 20
#define NNC 50
#define NNT 5

typedef unsigned long long ull;

__device__ float4 d_xmax4[NB * (NY / 4)];   // 4 MB scratch, L2-resident

__device__ __forceinline__ float sigmoidf_(float v) { return 1.f / (1.f + expf(-v)); }

#define FMA2(acc, a, b) asm("fma.rn.f32x2 %0, %1, %2, %0;" : "+l"(acc) : "l"(a), "l"(b))
#define PACK2(o, lo, hi) asm("mov.b64 %0, {%1, %2};" : "=l"(o) : "f"(lo), "f"(hi))
#define UNPACK2(lo, hi, in) asm("mov.b64 {%0, %1}, %2;" : "=f"(lo), "=f"(hi) : "l"(in))
#define FMAX4(m, v) do { \
    m.x = fmaxf(m.x, v.x); m.y = fmaxf(m.y, v.y); \
    m.z = fmaxf(m.z, v.z); m.w = fmaxf(m.w, v.w); } while (0)

#define CPASYNC16(saddr, gptr) \
    asm volatile("cp.async.ca.shared.global [%0], [%1], 16;" :: "r"(saddr), "l"(gptr))
#define CPCOMMIT() asm volatile("cp.async.commit_group;" ::: "memory")
#define CPWAIT2()  asm volatile("cp.async.wait_group 2;" ::: "memory")

// one 4-K step of a 4-row column GEMM, f32x2.
#define GSTEP(W, STRIDE, CC, XB, RS, I, ACC) do {                               \
    float _w0 = (W)[((I) + 0) * (STRIDE) + (CC)];                               \
    float _w1 = (W)[((I) + 1) * (STRIDE) + (CC)];                               \
    float _w2 = (W)[((I) + 2) * (STRIDE) + (CC)];                               \
    float _w3 = (W)[((I) + 3) * (STRIDE) + (CC)];                               \
    ull _wa, _wb; PACK2(_wa, _w0, _w1); PACK2(_wb, _w2, _w3);                   \
    _Pragma("unroll")                                                           \
    for (int _j = 0; _j < 4; _j++) {                                            \
        ulonglong2 _x = *reinterpret_cast<const ulonglong2*>(                   \
            &(XB)[_j * (RS) + (I)]);                                            \
        FMA2((ACC)[_j], _x.x, _wa);                                             \
        FMA2((ACC)[_j], _x.y, _wb);                                             \
    } } while (0)

__device__ __forceinline__ void head_sel(int c,
    const float* W_country, const float* W_type, const float* W_taste,
    const float* W_grape, const float* W_aroma,
    const float** Wp, int* stride, int* cc)
{
    if (c < NNC)       { *Wp = W_country; *stride = NNC; *cc = c; }
    else if (c == NNC) { *Wp = W_type;    *stride = 1;   *cc = 0; }
    else if (c < 56)   { *Wp = W_taste;   *stride = NNT; *cc = c - 51; }
    else if (c < 88)   { *Wp = W_grape;   *stride = NE;  *cc = c - 56; }
    else if (c < 120)  { *Wp = W_aroma;   *stride = NE;  *cc = c - 88; }
    else               { *Wp = W_country; *stride = NNC; *cc = 0; }   // dummy lanes
}

// ============== K1: pure max-pool stream (measured ~45us @ 5.95 TB/s) ==============
__global__ void maxpool_k(const float4* __restrict__ x4)
{
    int t  = blockIdx.x * 256 + threadIdx.x;   // 0 .. B*64-1
    int b  = t >> 6;
    int c4 = t & 63;
    const float4* p = x4 + (size_t)b * (NS * NY / 4) + c4;

    float4 m0 = p[0 * 64], m1 = p[1 * 64], m2 = p[2 * 64], m3 = p[3 * 64];
    #pragma unroll
    for (int s = 4; s < NS; s += 4) {
        float4 v0 = p[(s + 0) * 64];
        float4 v1 = p[(s + 1) * 64];
        float4 v2 = p[(s + 2) * 64];
        float4 v3 = p[(s + 3) * 64];
        FMAX4(m0, v0); FMAX4(m1, v1); FMAX4(m2, v2); FMAX4(m3, v3);
    }
    float4 r;
    r.x = fmaxf(fmaxf(m0.x, m1.x), fmaxf(m2.x, m3.x));
    r.y = fmaxf(fmaxf(m0.y, m1.y), fmaxf(m2.y, m3.y));
    r.z = fmaxf(fmaxf(m0.z, m1.z), fmaxf(m2.z, m3.z));
    r.w = fmaxf(fmaxf(m0.w, m1.w), fmaxf(m2.w, m3.w));
    d_xmax4[t] = r;
}

// ====== K2: MLP + heads + ragged; cp.async staged weight pipeline ======
#define NSTAGE 16            // 16 K-rows of W_common per stage (8 KB)
__global__ __launch_bounds__(256, 4) void mlp_k(
    const int*   __restrict__ grapes,
    const float* __restrict__ grapes_scales,
    const int*   __restrict__ aromas,
    const float* __restrict__ aromas_scales,
    const float* __restrict__ W_common, const float* __restrict__ b_common,
    const float* __restrict__ W_country, const float* __restrict__ b_country,
    const float* __restrict__ W_type,   const float* __restrict__ b_type,
    const float* __restrict__ W_taste,  const float* __restrict__ b_taste,
    const float* __restrict__ W_aroma,  const float* __restrict__ b_aroma,
    const float* __restrict__ W_grape,  const float* __restrict__ b_grape,
    const float* __restrict__ grapes_emb,
    const float* __restrict__ aroma_emb,
    float* __restrict__ out)
{
    __shared__ __align__(16) float wring[4][16 * NH];   // 32 KB weight ring
    __shared__ __align__(16) float x_sm[8 * NY];        // 8 KB
    __shared__ __align__(16) float ys[8 * NH];          // 4 KB
    __shared__ __align__(16) float yg_sm[8 * NE];       // 1 KB
    __shared__ __align__(16) float ya_sm[8 * NE];       // 1 KB

    const int tid  = threadIdx.x;
    const int b0   = blockIdx.x * 8;
    const int h    = tid & 127;
    const int half = tid >> 7;

    const float4* wg = reinterpret_cast<const float4*>(W_common);   // [256*128/4]

    // issue weight stages 0..2 immediately (overlap everything below)
    #pragma unroll
    for (int s = 0; s < 3; s++) {
        unsigned int sa = (unsigned int)__cvta_generic_to_shared(&wring[s][0]);
        CPASYNC16(sa + tid * 16,            wg + (size_t)s * 512 + tid);
        CPASYNC16(sa + (tid + 256) * 16,    wg + (size_t)s * 512 + tid + 256);
        CPCOMMIT();
    }

    // hoisted ragged indices/scales + "true" outputs
    int g_idx = 0, a_idx = 0; float a_sc = 0.f;
    if (tid < 64) {
        const int r = tid >> 3, k = tid & 7;
        g_idx = grapes[(b0 + r) * NKG + k];
        out[(size_t)NB * 64 + (size_t)(b0 + r) * NKG + k] =
            grapes_scales[(b0 + r) * NKG + k];
    } else if (tid < 224) {
        const int task = tid - 64;
        const int r = task / NKA, k = task % NKA;
        a_idx = aromas[(b0 + r) * NKA + k];
        a_sc  = aromas_scales[(b0 + r) * NKA + k];
        out[(size_t)NB * 92 + (size_t)(b0 + r) * NKA + k] = a_sc;
    }

    // load x tile [8,256] from L2-resident scratch
    {
        const float4* xm4 = d_xmax4 + (size_t)b0 * (NY / 4);
        reinterpret_cast<float4*>(x_sm)[tid]       = xm4[tid];
        reinterpret_cast<float4*>(x_sm)[tid + 256] = xm4[tid + 256];
    }
    __syncthreads();

    // ===== GEMM1: K=256 in 16 staged tiles of 16, weights via cp.async ring =====
    {
        const float* xb = &x_sm[4 * half * NY];
        ull acc[4] = {0ull, 0ull, 0ull, 0ull};
        #pragma unroll
        for (int s = 0; s < NSTAGE; s++) {
            CPWAIT2();                 // stage s complete (<=2 groups pending)
            __syncthreads();           // all threads' slices visible; ring[s-1&3] free
            const float* wsm = wring[s & 3];
            const float* xs2 = xb + 16 * s;
            #pragma unroll
            for (int q = 0; q < 4; q++)
                GSTEP(wsm, NH, h, xs2, NY, 4 * q, acc);
            if (s < NSTAGE - 3) {
                const int sn = s + 3;
                unsigned int sa = (unsigned int)__cvta_generic_to_shared(&wring[sn & 3][0]);
                CPASYNC16(sa + tid * 16,         wg + (size_t)sn * 512 + tid);
                CPASYNC16(sa + (tid + 256) * 16, wg + (size_t)sn * 512 + tid + 256);
                CPCOMMIT();
            } else {
                CPCOMMIT();            // keep group count in step for CPWAIT2
            }
        }
        const float bcm = b_common[h];
        #pragma unroll
        for (int j = 0; j < 4; j++) {
            float lo, hi; UNPACK2(lo, hi, acc[j]);
            float v = lo + hi + bcm;
            ys[(4 * half + j) * NH + h] = (v > 0.f) ? v : expm1f(v);
        }
    }
    __syncthreads();

    // ===== heads: full K=128, direct LDG (60KB head weights are L1-resident) =====
    {
        const float* Wp; int hstride, hcc;
        head_sel(h, W_country, W_type, W_taste, W_grape, W_aroma, &Wp, &hstride, &hcc);
        const float* yb = &ys[4 * half * NH];
        ull acch[4] = {0ull, 0ull, 0ull, 0ull};
        #pragma unroll 4
        for (int it = 0; it < 32; it++)
            GSTEP(Wp, hstride, hcc, yb, NH, 4 * it, acch);

        const int gb = b0 + 4 * half;
        float s_[4];
        #pragma unroll
        for (int j = 0; j < 4; j++) {
            float lo, hi; UNPACK2(lo, hi, acch[j]);
            s_[j] = lo + hi;
        }
        if (h < NNC) {
            float bb = b_country[h];
            #pragma unroll
            for (int j = 0; j < 4; j++)
                out[(size_t)(gb + j) * NNC + h] = s_[j] + bb;
        } else if (h == NNC) {
            float bb = b_type[0];
            #pragma unroll
            for (int j = 0; j < 4; j++)
                out[(size_t)NB * NNC + (gb + j)] = sigmoidf_(s_[j] + bb);
        } else if (h < 56) {
            const int cc = h - 51;
            float bb = b_taste[cc];
            #pragma unroll
            for (int j = 0; j < 4; j++)
                out[(size_t)NB * 51 + (size_t)(gb + j) * NNT + cc] = sigmoidf_(s_[j] + bb);
        } else if (h < 88) {
            const int e = h - 56;
            float bb = b_grape[e];
            #pragma unroll
            for (int j = 0; j < 4; j++) yg_sm[(4 * half + j) * NE + e] = s_[j] + bb;
        } else if (h < 120) {
            const int e = h - 88;
            float bb = b_aroma[e];
            #pragma unroll
            for (int j = 0; j < 4; j++) ya_sm[(4 * half + j) * NE + e] = s_[j] + bb;
        }
    }
    __syncthreads();

    // ===== ragged predictions =====
    if (tid < 64) {
        const int r = tid >> 3, k = tid & 7;
        const int b = b0 + r;
        const float4* emb = reinterpret_cast<const float4*>(grapes_emb) + (size_t)g_idx * (NE / 4);
        const float4* yv4 = reinterpret_cast<const float4*>(&yg_sm[r * NE]);
        float acc2 = 0.f;
        #pragma unroll
        for (int i = 0; i < NE / 4; i++) {
            float4 ev = emb[i], yv = yv4[i];
            acc2 += ev.x * yv.x + ev.y * yv.y + ev.z * yv.z + ev.w * yv.w;
        }
        float mask = (g_idx != 0) ? 1.f : 0.f;
        out[(size_t)NB * 56 + (size_t)b * NKG + k] = sigmoidf_(acc2) * mask;
    } else if (tid < 224) {
        const int task = tid - 64;
        const int r = task / NKA, k = task % NKA;
        const int b = b0 + r;
        const float4* emb = reinterpret_cast<const float4*>(aroma_emb) + (size_t)a_idx * (NE / 4);
        const float4* yv4 = reinterpret_cast<const float4*>(&ya_sm[r * NE]);
        float acc2 = 0.f;
        #pragma unroll
        for (int i = 0; i < NE / 4; i++) {
            float4 ev = emb[i], yv = yv4[i];
            acc2 += ev.x * yv.x + ev.y * yv.y + ev.z * yv.z + ev.w * yv.w;
        }
        float mask = (a_sc != 0.f) ? 1.f : 0.f;
        out[(size_t)NB * 72 + (size_t)b * NKA + k] = sigmoidf_(acc2) * mask;
    }
}

extern "C" void kernel_launch(void* const* d_in, const int* in_sizes, int n_in,
                              void* d_out, int out_size) {
    const float* x_enc          = (const float*)d_in[0];
    const int*   grapes         = (const int*)  d_in[1];
    const float* grapes_scales  = (const float*)d_in[2];
    const int*   aromas         = (const int*)  d_in[3];
    const float* aromas_scales  = (const float*)d_in[4];
    const float* W_common       = (const float*)d_in[5];
    const float* b_common       = (const float*)d_in[6];
    const float* W_country      = (const float*)d_in[7];
    const float* b_country      = (const float*)d_in[8];
    const float* W_type         = (const float*)d_in[9];
    const float* b_type         = (const float*)d_in[10];
    const float* W_taste        = (const float*)d_in[11];
    const float* b_taste        = (const float*)d_in[12];
    const float* W_aroma        = (const float*)d_in[13];
    const float* b_aroma        = (const float*)d_in[14];
    const float* W_grape        = (const float*)d_in[15];
    const float* b_grape        = (const float*)d_in[16];
    const float* grapes_emb     = (const float*)d_in[17];
    const float* aroma_emb      = (const float*)d_in[18];
    float* out = (float*)d_out;

    maxpool_k<<<NB * (NY / 4) / 256, 256>>>(reinterpret_cast<const float4*>(x_enc));
    mlp_k<<<NB / 8, 256>>>(grapes, grapes_scales, aromas, aromas_scales,
                           W_common, b_common, W_country, b_country,
                           W_type, b_type, W_taste, b_taste,
                           W_aroma, b_aroma, W_grape, b_grape,
                           grapes_emb, aroma_emb, out);
}

// round 17
// speedup vs baseline: 1.1210x; 1.1210x over previous
#include <cuda_runtime.h>
#include <stdint.h>
#include <math.h>

#define NB 4096
#define NS 64
#define NY 256
#define NH 128
#define NE 32
#define NKG 8
#define NKA 20
#define NNC 50
#define NNT 5
#define NPOOLBLK (NB / 4)        // 1024 pool blocks (4 rows each)
#define NMLPBLK  (NB / 8)        // 512 mlp blocks (8 rows each)

typedef unsigned long long ull;

__device__ float4 d_xmax4[NB * (NY / 4)];   // 4 MB scratch, L2-resident
__device__ int    d_flags[NPOOLBLK];

__device__ __forceinline__ float sigmoidf_(float v) { return 1.f / (1.f + expf(-v)); }

#define FMA2(acc, a, b) asm("fma.rn.f32x2 %0, %1, %2, %0;" : "+l"(acc) : "l"(a), "l"(b))
#define PACK2(o, lo, hi) asm("mov.b64 %0, {%1, %2};" : "=l"(o) : "f"(lo), "f"(hi))
#define UNPACK2(lo, hi, in) asm("mov.b64 {%0, %1}, %2;" : "=f"(lo), "=f"(hi) : "l"(in))
#define FMAX4(m, v) do { \
    m.x = fmaxf(m.x, v.x); m.y = fmaxf(m.y, v.y); \
    m.z = fmaxf(m.z, v.z); m.w = fmaxf(m.w, v.w); } while (0)

#define GSTEP(W, STRIDE, CC, XB, RS, I, ACC) do {                               \
    float _w0 = (W)[((I) + 0) * (STRIDE) + (CC)];                               \
    float _w1 = (W)[((I) + 1) * (STRIDE) + (CC)];                               \
    float _w2 = (W)[((I) + 2) * (STRIDE) + (CC)];                               \
    float _w3 = (W)[((I) + 3) * (STRIDE) + (CC)];                               \
    ull _wa, _wb; PACK2(_wa, _w0, _w1); PACK2(_wb, _w2, _w3);                   \
    _Pragma("unroll")                                                           \
    for (int _j = 0; _j < 4; _j++) {                                            \
        ulonglong2 _x = *reinterpret_cast<const ulonglong2*>(                   \
            &(XB)[_j * (RS) + (I)]);                                            \
        FMA2((ACC)[_j], _x.x, _wa);                                             \
        FMA2((ACC)[_j], _x.y, _wb);                                             \
    } } while (0)

__device__ __forceinline__ void head_sel(int c,
    const float* W_country, const float* W_type, const float* W_taste,
    const float* W_grape, const float* W_aroma,
    const float** Wp, int* stride, int* cc)
{
    if (c < NNC)       { *Wp = W_country; *stride = NNC; *cc = c; }
    else if (c == NNC) { *Wp = W_type;    *stride = 1;   *cc = 0; }
    else if (c < 56)   { *Wp = W_taste;   *stride = NNT; *cc = c - 51; }
    else if (c < 88)   { *Wp = W_grape;   *stride = NE;  *cc = c - 56; }
    else if (c < 120)  { *Wp = W_aroma;   *stride = NE;  *cc = c - 88; }
    else               { *Wp = W_country; *stride = NNC; *cc = 0; }   // dummy lanes
}

// blocks [0, NPOOLBLK) = pool (dispatched first, stream at full rate);
// blocks [NPOOLBLK, NPOOLBLK+NMLPBLK) = mlp (trickle in as pool retires).
__global__ __launch_bounds__(256, 4) void wine_pc2(
    const float4* __restrict__ x4,
    const int*   __restrict__ grapes,
    const float* __restrict__ grapes_scales,
    const int*   __restrict__ aromas,
    const float* __restrict__ aromas_scales,
    const float* __restrict__ W_common, const float* __restrict__ b_common,
    const float* __restrict__ W_country, const float* __restrict__ b_country,
    const float* __restrict__ W_type,   const float* __restrict__ b_type,
    const float* __restrict__ W_taste,  const float* __restrict__ b_taste,
    const float* __restrict__ W_aroma,  const float* __restrict__ b_aroma,
    const float* __restrict__ W_grape,  const float* __restrict__ b_grape,
    const float* __restrict__ grapes_emb,
    const float* __restrict__ aroma_emb,
    float* __restrict__ out)
{
    const int tid = threadIdx.x;

    if (blockIdx.x < NPOOLBLK) {
        // ====================== POOL role: stream 4 batch rows ======================
        const int pblk = blockIdx.x;
        const int g    = pblk * 256 + tid;    // global (row, col4) task
        const int b    = g >> 6;
        const int c4   = g & 63;
        const float4* p = x4 + (size_t)b * (NS * NY / 4) + c4;

        float4 m0 = p[0 * 64], m1 = p[1 * 64], m2 = p[2 * 64], m3 = p[3 * 64];
        #pragma unroll
        for (int s = 4; s < NS; s += 4) {
            float4 v0 = p[(s + 0) * 64];
            float4 v1 = p[(s + 1) * 64];
            float4 v2 = p[(s + 2) * 64];
            float4 v3 = p[(s + 3) * 64];
            FMAX4(m0, v0); FMAX4(m1, v1); FMAX4(m2, v2); FMAX4(m3, v3);
        }
        float4 r;
        r.x = fmaxf(fmaxf(m0.x, m1.x), fmaxf(m2.x, m3.x));
        r.y = fmaxf(fmaxf(m0.y, m1.y), fmaxf(m2.y, m3.y));
        r.z = fmaxf(fmaxf(m0.z, m1.z), fmaxf(m2.z, m3.z));
        r.w = fmaxf(fmaxf(m0.w, m1.w), fmaxf(m2.w, m3.w));
        d_xmax4[g] = r;

        __syncthreads();
        __threadfence();
        if (tid == 0) atomicExch(&d_flags[pblk], 1);
        return;
    }

    // ========================= MLP role: 8 batch rows =========================
    __shared__ __align__(16) float x_sm[8 * NY];    // 8 KB
    __shared__ __align__(16) float ys[8 * NH];      // 4 KB
    __shared__ __align__(16) float yg_sm[8 * NE];   // 1 KB
    __shared__ __align__(16) float ya_sm[8 * NE];   // 1 KB

    const int m    = blockIdx.x - NPOOLBLK;
    const int b0   = m * 8;
    const int h    = tid & 127;
    const int half = tid >> 7;

    // hoisted ragged indices/scales + "true" outputs (independent of pool)
    int g_idx = 0, a_idx = 0; float a_sc = 0.f;
    if (tid < 64) {
        const int r = tid >> 3, k = tid & 7;
        g_idx = grapes[(b0 + r) * NKG + k];
        out[(size_t)NB * 64 + (size_t)(b0 + r) * NKG + k] =
            grapes_scales[(b0 + r) * NKG + k];
    } else if (tid < 224) {
        const int task = tid - 64;
        const int r = task / NKA, k = task % NKA;
        a_idx = aromas[(b0 + r) * NKA + k];
        a_sc  = aromas_scales[(b0 + r) * NKA + k];
        out[(size_t)NB * 92 + (size_t)(b0 + r) * NKA + k] = a_sc;
    }

    // wait for the two producer pool blocks
    if (tid == 0) {
        volatile int* fl = d_flags;
        while (fl[2 * m]     == 0) __nanosleep(200);
        while (fl[2 * m + 1] == 0) __nanosleep(200);
        __threadfence();
    }
    __syncthreads();

    // load x tile [8,256] from L2 (bypass L1: __ldcg; L2 is the coherence point)
    {
        const float4* xm4 = d_xmax4 + (size_t)b0 * (NY / 4);
        reinterpret_cast<float4*>(x_sm)[tid]       = __ldcg(&xm4[tid]);
        reinterpret_cast<float4*>(x_sm)[tid + 256] = __ldcg(&xm4[tid + 256]);
    }
    __syncthreads();

    // GEMM1: full K=256, direct accumulation
    {
        const float* xb = &x_sm[4 * half * NY];
        ull acc[4] = {0ull, 0ull, 0ull, 0ull};
        #pragma unroll 4
        for (int it = 0; it < 64; it++)
            GSTEP(W_common, NH, h, xb, NY, 4 * it, acc);
        const float bcm = b_common[h];
        #pragma unroll
        for (int j = 0; j < 4; j++) {
            float lo, hi; UNPACK2(lo, hi, acc[j]);
            float v = lo + hi + bcm;
            ys[(4 * half + j) * NH + h] = (v > 0.f) ? v : expm1f(v);
        }
    }
    __syncthreads();

    // heads: full K=128, direct accumulation
    {
        const float* Wp; int hstride, hcc;
        head_sel(h, W_country, W_type, W_taste, W_grape, W_aroma, &Wp, &hstride, &hcc);
        const float* yb = &ys[4 * half * NH];
        ull acch[4] = {0ull, 0ull, 0ull, 0ull};
        #pragma unroll 4
        for (int it = 0; it < 32; it++)
            GSTEP(Wp, hstride, hcc, yb, NH, 4 * it, acch);

        const int gb = b0 + 4 * half;
        float s_[4];
        #pragma unroll
        for (int j = 0; j < 4; j++) {
            float lo, hi; UNPACK2(lo, hi, acch[j]);
            s_[j] = lo + hi;
        }
        if (h < NNC) {
            float bb = b_country[h];
            #pragma unroll
            for (int j = 0; j < 4; j++)
                out[(size_t)(gb + j) * NNC + h] = s_[j] + bb;
        } else if (h == NNC) {
            float bb = b_type[0];
            #pragma unroll
            for (int j = 0; j < 4; j++)
                out[(size_t)NB * NNC + (gb + j)] = sigmoidf_(s_[j] + bb);
        } else if (h < 56) {
            const int cc = h - 51;
            float bb = b_taste[cc];
            #pragma unroll
            for (int j = 0; j < 4; j++)
                out[(size_t)NB * 51 + (size_t)(gb + j) * NNT + cc] = sigmoidf_(s_[j] + bb);
        } else if (h < 88) {
            const int e = h - 56;
            float bb = b_grape[e];
            #pragma unroll
            for (int j = 0; j < 4; j++) yg_sm[(4 * half + j) * NE + e] = s_[j] + bb;
        } else if (h < 120) {
            const int e = h - 88;
            float bb = b_aroma[e];
            #pragma unroll
            for (int j = 0; j < 4; j++) ya_sm[(4 * half + j) * NE + e] = s_[j] + bb;
        }
    }
    __syncthreads();

    // ragged predictions
    if (tid < 64) {
        const int r = tid >> 3, k = tid & 7;
        const int b = b0 + r;
        const float4* emb = reinterpret_cast<const float4*>(grapes_emb) + (size_t)g_idx * (NE / 4);
        const float4* yv4 = reinterpret_cast<const float4*>(&yg_sm[r * NE]);
        float acc2 = 0.f;
        #pragma unroll
        for (int i = 0; i < NE / 4; i++) {
            float4 ev = emb[i], yv = yv4[i];
            acc2 += ev.x * yv.x + ev.y * yv.y + ev.z * yv.z + ev.w * yv.w;
        }
        float mask = (g_idx != 0) ? 1.f : 0.f;
        out[(size_t)NB * 56 + (size_t)b * NKG + k] = sigmoidf_(acc2) * mask;
    } else if (tid < 224) {
        const int task = tid - 64;
        const int r = task / NKA, k = task % NKA;
        const int b = b0 + r;
        const float4* emb = reinterpret_cast<const float4*>(aroma_emb) + (size_t)a_idx * (NE / 4);
        const float4* yv4 = reinterpret_cast<const float4*>(&ya_sm[r * NE]);
        float acc2 = 0.f;
        #pragma unroll
        for (int i = 0; i < NE / 4; i++) {
            float4 ev = emb[i], yv = yv4[i];
            acc2 += ev.x * yv.x + ev.y * yv.y + ev.z * yv.z + ev.w * yv.w;
        }
        float mask = (a_sc != 0.f) ? 1.f : 0.f;
        out[(size_t)NB * 72 + (size_t)b * NKA + k] = sigmoidf_(acc2) * mask;
    }
}

extern "C" void kernel_launch(void* const* d_in, const int* in_sizes, int n_in,
                              void* d_out, int out_size) {
    const float* x_enc          = (const float*)d_in[0];
    const int*   grapes         = (const int*)  d_in[1];
    const float* grapes_scales  = (const float*)d_in[2];
    const int*   aromas         = (const int*)  d_in[3];
    const float* aromas_scales  = (const float*)d_in[4];
    const float* W_common       = (const float*)d_in[5];
    const float* b_common       = (const float*)d_in[6];
    const float* W_country      = (const float*)d_in[7];
    const float* b_country      = (const float*)d_in[8];
    const float* W_type         = (const float*)d_in[9];
    const float* b_type         = (const float*)d_in[10];
    const float* W_taste        = (const float*)d_in[11];
    const float* b_taste        = (const float*)d_in[12];
    const float* W_aroma        = (const float*)d_in[13];
    const float* b_aroma        = (const float*)d_in[14];
    const float* W_grape        = (const float*)d_in[15];
    const float* b_grape        = (const float*)d_in[16];
    const float* grapes_emb     = (const float*)d_in[17];
    const float* aroma_emb      = (const float*)d_in[18];
    float* out = (float*)d_out;

    // reset producer flags (graph-capturable memset node; no allocation)
    void* flags_ptr = nullptr;
    cudaGetSymbolAddress(&flags_ptr, d_flags);
    cudaMemsetAsync(flags_ptr, 0, NPOOLBLK * sizeof(int));

    wine_pc2<<<NPOOLBLK + NMLPBLK, 256>>>(reinterpret_cast<const float4*>(x_enc),
                                          grapes, grapes_scales, aromas, aromas_scales,
                                          W_common, b_common, W_country, b_country,
                                          W_type, b_type, W_taste, b_taste,
                                          W_aroma, b_aroma, W_grape, b_grape,
                                          grapes_emb, aroma_emb, out);
}